// round 3
// baseline (speedup 1.0000x reference)
#include <cuda_runtime.h>
#include <cstddef>

#define N_NODES 100000
#define NNZ     3200000

// ---------------- static scratch (no allocation allowed) ----------------
// Single 204.8MB arena; the two 128-wide buffers alias the second 256-wide
// region (never simultaneously live with it). Kernels resolve addresses
// device-side from a selector so the host path is kernel launches ONLY.
//   sel 0: buf256A = scratch
//   sel 1: buf256B = scratch + N*256
//   sel 2: buf128A = scratch + N*256            (aliases buf256B lower half)
//   sel 3: buf128B = scratch + N*256 + N*128    (aliases buf256B upper half)
__device__ float g_scratch[(size_t)N_NODES * 512];

__device__ __forceinline__ float* buf(int sel) {
    switch (sel) {
        case 0:  return g_scratch;
        case 1:  return g_scratch + (size_t)N_NODES * 256;
        case 2:  return g_scratch + (size_t)N_NODES * 256;
        default: return g_scratch + (size_t)N_NODES * 256 + (size_t)N_NODES * 128;
    }
}

// ---------------- zero fill ----------------
template<int D>
__global__ void zero_kernel(int sel) {
    float4* p = (float4*)buf(sel);
    size_t n4 = (size_t)N_NODES * D / 4;
    size_t i = (size_t)blockIdx.x * blockDim.x + threadIdx.x;
    size_t stride = (size_t)gridDim.x * blockDim.x;
    float4 z = make_float4(0.f, 0.f, 0.f, 0.f);
    for (; i < n4; i += stride) p[i] = z;
}

// ---------------- vector reduction to global ----------------
__device__ __forceinline__ void red_add_v4(float4* addr, float x, float y, float z, float w) {
    asm volatile("red.global.add.v4.f32 [%0], {%1, %2, %3, %4};"
                 :: "l"(addr), "f"(x), "f"(y), "f"(z), "f"(w)
                 : "memory");
}

// ---------------- SpMM: out[row] += val * h[col], scatter-add ----------------
// One warp processes 32 edges: coalesced edge loads, shuffle-broadcast each
// edge, then 32 lanes cover D floats with float4 gathers + v4 reductions.
// in_sel/out_sel: -1 = external pointer (h_ext/out_ext), else scratch selector.
template<int D>
__global__ void __launch_bounds__(256) spmm_kernel(
    const float* __restrict__ h_ext,
    float*       __restrict__ out_ext,
    int in_sel, int out_sel,
    const int*   __restrict__ rows,
    const int*   __restrict__ cols,
    const float* __restrict__ vals)
{
    const float* h   = (in_sel  < 0) ? h_ext   : buf(in_sel);
    float*       out = (out_sel < 0) ? out_ext : buf(out_sel);

    int lane = threadIdx.x & 31;
    int gw   = (int)((blockIdx.x * blockDim.x + threadIdx.x) >> 5);
    int base = gw * 32;
    if (base >= NNZ) return;

    int   r = rows[base + lane];
    int   c = cols[base + lane];
    float v = vals[base + lane];

    #pragma unroll 4
    for (int j = 0; j < 32; j++) {
        int   cj = __shfl_sync(0xffffffffu, c, j);
        int   rj = __shfl_sync(0xffffffffu, r, j);
        float vj = __shfl_sync(0xffffffffu, v, j);

        const float4* src = (const float4*)(h   + (size_t)cj * D);
        float4*       dst = (float4*)      (out + (size_t)rj * D);

        #pragma unroll
        for (int i = 0; i < D / 128; i++) {
            float4 g = __ldg(src + lane + i * 32);
            red_add_v4(dst + lane + i * 32,
                       g.x * vj, g.y * vj, g.z * vj, g.w * vj);
        }
    }
}

// ---------------- GEMM: C[M,N] = act(A[M,K] @ W[N,K]^T) ----------------
// 64x64 block tile, BK=16, 4x4 register micro-tile, 256 threads.
template<int K, int N, bool RELU>
__global__ void __launch_bounds__(256) gemm_nt(
    int a_sel,
    const float* __restrict__ W,
    float*       __restrict__ C_ext,
    int c_sel)
{
    const float* A = buf(a_sel);
    float*       C = (c_sel < 0) ? C_ext : buf(c_sel);

    constexpr int BM = 64, BN = 64, BK = 16;
    constexpr int M = N_NODES;
    __shared__ __align__(16) float As[BK][BM];
    __shared__ __align__(16) float Bs[BK][BN];

    int tid  = threadIdx.x;
    int row0 = blockIdx.y * BM;
    int col0 = blockIdx.x * BN;
    int ty   = tid >> 4;       // 0..15  (row group)
    int tx   = tid & 15;       // 0..15  (col group)

    // loader mapping: each thread loads one float4 (k-contiguous), scatters transposed
    int lm = tid >> 2;         // 0..63
    int lk = (tid & 3) * 4;    // 0,4,8,12

    float acc[4][4] = {};

    for (int k0 = 0; k0 < K; k0 += BK) {
        float4 av = make_float4(0.f, 0.f, 0.f, 0.f);
        int ar = row0 + lm;
        if (ar < M)
            av = *(const float4*)&A[(size_t)ar * K + k0 + lk];
        As[lk + 0][lm] = av.x; As[lk + 1][lm] = av.y;
        As[lk + 2][lm] = av.z; As[lk + 3][lm] = av.w;

        float4 bv = *(const float4*)&W[(size_t)(col0 + lm) * K + k0 + lk];
        Bs[lk + 0][lm] = bv.x; Bs[lk + 1][lm] = bv.y;
        Bs[lk + 2][lm] = bv.z; Bs[lk + 3][lm] = bv.w;

        __syncthreads();

        #pragma unroll
        for (int kk = 0; kk < BK; kk++) {
            float4 a = *(const float4*)&As[kk][ty * 4];
            float4 b = *(const float4*)&Bs[kk][tx * 4];
            acc[0][0] += a.x * b.x; acc[0][1] += a.x * b.y;
            acc[0][2] += a.x * b.z; acc[0][3] += a.x * b.w;
            acc[1][0] += a.y * b.x; acc[1][1] += a.y * b.y;
            acc[1][2] += a.y * b.z; acc[1][3] += a.y * b.w;
            acc[2][0] += a.z * b.x; acc[2][1] += a.z * b.y;
            acc[2][2] += a.z * b.z; acc[2][3] += a.z * b.w;
            acc[3][0] += a.w * b.x; acc[3][1] += a.w * b.y;
            acc[3][2] += a.w * b.z; acc[3][3] += a.w * b.w;
        }
        __syncthreads();
    }

    #pragma unroll
    for (int i = 0; i < 4; i++) {
        int r = row0 + ty * 4 + i;
        if (r < M) {
            float4 o;
            o.x = acc[i][0]; o.y = acc[i][1]; o.z = acc[i][2]; o.w = acc[i][3];
            if (RELU) {
                o.x = fmaxf(o.x, 0.f); o.y = fmaxf(o.y, 0.f);
                o.z = fmaxf(o.z, 0.f); o.w = fmaxf(o.w, 0.f);
            }
            *(float4*)&C[(size_t)r * N + col0 + tx * 4] = o;
        }
    }
}

// ---------------- launch ----------------
extern "C" void kernel_launch(void* const* d_in, const int* in_sizes, int n_in,
                              void* d_out, int out_size)
{
    const float* x  = (const float*)d_in[0];
    const int*   er = (const int*)  d_in[1];
    const int*   ec = (const int*)  d_in[2];
    const float* ev = (const float*)d_in[3];
    const float* W1 = (const float*)d_in[4];
    const float* W2 = (const float*)d_in[5];
    float* out = (float*)d_out;

    const int ZB = 1024;                 // grid for zeroing
    const int SPMM_BLOCKS = NNZ / 256;   // warp per 32 edges, 8 warps/block

    // layer 1: propagate x twice (d=128): x -> buf128A(2) -> buf128B(3)
    zero_kernel<128><<<ZB, 256>>>(2);
    spmm_kernel<128><<<SPMM_BLOCKS, 256>>>(x, nullptr, -1, 2, er, ec, ev);
    zero_kernel<128><<<ZB, 256>>>(3);
    spmm_kernel<128><<<SPMM_BLOCKS, 256>>>(nullptr, nullptr, 2, 3, er, ec, ev);

    // h = relu(h @ W1^T) : buf128B(3) [100000,128] x [256,128]^T -> buf256A(0)
    {
        dim3 grid(256 / 64, (N_NODES + 63) / 64);
        gemm_nt<128, 256, true><<<grid, 256>>>(3, W1, nullptr, 0);
    }

    // layer 2: propagate twice (d=256): buf256A(0) -> buf256B(1) -> buf256A(0)
    zero_kernel<256><<<ZB, 256>>>(1);
    spmm_kernel<256><<<SPMM_BLOCKS, 256>>>(nullptr, nullptr, 0, 1, er, ec, ev);
    zero_kernel<256><<<ZB, 256>>>(0);
    spmm_kernel<256><<<SPMM_BLOCKS, 256>>>(nullptr, nullptr, 1, 0, er, ec, ev);

    // out = h @ W2^T : buf256A(0) [100000,256] x [128,256]^T -> d_out [100000,128]
    {
        dim3 grid(128 / 64, (N_NODES + 63) / 64);
        gemm_nt<256, 128, false><<<grid, 256>>>(0, W2, out, -1);
    }
}

// round 4
// speedup vs baseline: 1.8501x; 1.8501x over previous
#include <cuda_runtime.h>
#include <cstddef>

#define N_NODES 100000
#define NNZ     3200000

// ---------------- static scratch (no allocation allowed) ----------------
//   sel 0: bA128 = arena                  (N*128 floats)
//   sel 1: bB128 = arena + N*128          (N*128 floats)
//   sel 2: b256  = arena + N*256          (N*256 floats)
__device__ float g_scratch[(size_t)N_NODES * 512];

__device__ __forceinline__ float* buf(int sel) {
    switch (sel) {
        case 0:  return g_scratch;
        case 1:  return g_scratch + (size_t)N_NODES * 128;
        default: return g_scratch + (size_t)N_NODES * 256;
    }
}

// ---------------- zero fill (sel >= 0: scratch, sel < 0: external ptr) ----------------
__global__ void zero_kernel(float4* __restrict__ ext, int sel, size_t n4) {
    float4* p = (sel < 0) ? ext : (float4*)buf(sel);
    size_t i = (size_t)blockIdx.x * blockDim.x + threadIdx.x;
    size_t stride = (size_t)gridDim.x * blockDim.x;
    float4 z = make_float4(0.f, 0.f, 0.f, 0.f);
    for (; i < n4; i += stride) p[i] = z;
}

// ---------------- vector reduction to global ----------------
__device__ __forceinline__ void red_add_v4(float4* addr, float x, float y, float z, float w) {
    asm volatile("red.global.add.v4.f32 [%0], {%1, %2, %3, %4};"
                 :: "l"(addr), "f"(x), "f"(y), "f"(z), "f"(w)
                 : "memory");
}

// ---------------- SpMM (d=128): out[row] += val * h[col] ----------------
// One warp per 32 edges: coalesced edge loads, shuffle-broadcast per edge,
// 32 lanes x float4 cover the 128-wide row. Atomic v4 reductions (no return).
__global__ void __launch_bounds__(256) spmm128_kernel(
    const float* __restrict__ h_ext,
    float*       __restrict__ out_ext,
    int in_sel, int out_sel,
    const int*   __restrict__ rows,
    const int*   __restrict__ cols,
    const float* __restrict__ vals)
{
    const float* h   = (in_sel  < 0) ? h_ext   : buf(in_sel);
    float*       out = (out_sel < 0) ? out_ext : buf(out_sel);

    int lane = threadIdx.x & 31;
    int gw   = (int)((blockIdx.x * blockDim.x + threadIdx.x) >> 5);
    int base = gw * 32;
    if (base >= NNZ) return;

    int   r = rows[base + lane];
    int   c = cols[base + lane];
    float v = vals[base + lane];

    #pragma unroll 4
    for (int j = 0; j < 32; j++) {
        int   cj = __shfl_sync(0xffffffffu, c, j);
        int   rj = __shfl_sync(0xffffffffu, r, j);
        float vj = __shfl_sync(0xffffffffu, v, j);

        const float4* src = (const float4*)(h   + (size_t)cj * 128);
        float4*       dst = (float4*)      (out + (size_t)rj * 128);

        float4 g = __ldg(src + lane);
        red_add_v4(dst + lane, g.x * vj, g.y * vj, g.z * vj, g.w * vj);
    }
}

// ---------------- GEMM: C[M,N] = act(A[M,K] @ W[N,K]^T) ----------------
// 128x128 block tile, BK=8, 8x8 micro-tile (4+4 split), 256 threads.
template<int K, int N, bool RELU>
__global__ void __launch_bounds__(256) gemm_nt(
    int a_sel,
    const float* __restrict__ W,
    float*       __restrict__ C_ext,
    int c_sel)
{
    const float* A = buf(a_sel);
    float*       C = (c_sel < 0) ? C_ext : buf(c_sel);

    constexpr int BM = 128, BN = 128, BK = 8;
    constexpr int M = N_NODES;
    __shared__ __align__(16) float As[BK][BM];
    __shared__ __align__(16) float Bs[BK][BN];

    int tid  = threadIdx.x;
    int row0 = blockIdx.y * BM;
    int col0 = blockIdx.x * BN;

    // loader mapping: 2 threads per row, each loads a float4 of K
    int lm = tid >> 1;           // 0..127
    int lk = (tid & 1) * 4;      // 0 or 4

    // compute mapping
    int ty = tid >> 4;           // 0..15
    int tx = tid & 15;           // 0..15

    float acc[2][2][4][4] = {};  // [ri][ci][i][j]

    for (int k0 = 0; k0 < K; k0 += BK) {
        float4 av = make_float4(0.f, 0.f, 0.f, 0.f);
        int ar = row0 + lm;
        if (ar < M)
            av = *(const float4*)&A[(size_t)ar * K + k0 + lk];
        As[lk + 0][lm] = av.x; As[lk + 1][lm] = av.y;
        As[lk + 2][lm] = av.z; As[lk + 3][lm] = av.w;

        float4 bv = *(const float4*)&W[(size_t)(col0 + lm) * K + k0 + lk];
        Bs[lk + 0][lm] = bv.x; Bs[lk + 1][lm] = bv.y;
        Bs[lk + 2][lm] = bv.z; Bs[lk + 3][lm] = bv.w;

        __syncthreads();

        #pragma unroll
        for (int kk = 0; kk < BK; kk++) {
            float4 a0 = *(const float4*)&As[kk][ty * 4];
            float4 a1 = *(const float4*)&As[kk][64 + ty * 4];
            float4 b0 = *(const float4*)&Bs[kk][tx * 4];
            float4 b1 = *(const float4*)&Bs[kk][64 + tx * 4];
            float ar4[2][4] = {{a0.x, a0.y, a0.z, a0.w}, {a1.x, a1.y, a1.z, a1.w}};
            float br4[2][4] = {{b0.x, b0.y, b0.z, b0.w}, {b1.x, b1.y, b1.z, b1.w}};
            #pragma unroll
            for (int ri = 0; ri < 2; ri++)
                #pragma unroll
                for (int ci = 0; ci < 2; ci++)
                    #pragma unroll
                    for (int i = 0; i < 4; i++)
                        #pragma unroll
                        for (int j = 0; j < 4; j++)
                            acc[ri][ci][i][j] += ar4[ri][i] * br4[ci][j];
        }
        __syncthreads();
    }

    #pragma unroll
    for (int ri = 0; ri < 2; ri++) {
        #pragma unroll
        for (int i = 0; i < 4; i++) {
            int r = row0 + ri * 64 + ty * 4 + i;
            if (r < M) {
                #pragma unroll
                for (int ci = 0; ci < 2; ci++) {
                    float4 o;
                    o.x = acc[ri][ci][i][0]; o.y = acc[ri][ci][i][1];
                    o.z = acc[ri][ci][i][2]; o.w = acc[ri][ci][i][3];
                    if (RELU) {
                        o.x = fmaxf(o.x, 0.f); o.y = fmaxf(o.y, 0.f);
                        o.z = fmaxf(o.z, 0.f); o.w = fmaxf(o.w, 0.f);
                    }
                    *(float4*)&C[(size_t)r * N + col0 + ci * 64 + tx * 4] = o;
                }
            }
        }
    }
}

// ---------------- launch ----------------
extern "C" void kernel_launch(void* const* d_in, const int* in_sizes, int n_in,
                              void* d_out, int out_size)
{
    const float* x  = (const float*)d_in[0];
    const int*   er = (const int*)  d_in[1];
    const int*   ec = (const int*)  d_in[2];
    const float* ev = (const float*)d_in[3];
    const float* W1 = (const float*)d_in[4];
    const float* W2 = (const float*)d_in[5];
    float* out = (float*)d_out;

    const size_t n128_4 = (size_t)N_NODES * 128 / 4;
    const int ZB = 1024;
    const int SPMM_BLOCKS = NNZ / 256;   // warp per 32 edges, 8 warps/block

    // layer 1: s = A (A x)   (all at d=128)
    zero_kernel<<<ZB, 256>>>(nullptr, 0, n128_4);
    spmm128_kernel<<<SPMM_BLOCKS, 256>>>(x, nullptr, -1, 0, er, ec, ev);
    zero_kernel<<<ZB, 256>>>(nullptr, 1, n128_4);
    spmm128_kernel<<<SPMM_BLOCKS, 256>>>(nullptr, nullptr, 0, 1, er, ec, ev);

    // h = relu(s @ W1^T) : [100000,128] x [256,128]^T -> b256
    {
        dim3 grid(256 / 128, (N_NODES + 127) / 128);
        gemm_nt<128, 256, true><<<grid, 256>>>(1, W1, nullptr, 2);
    }

    // g = h @ W2^T : [100000,256] x [128,256]^T -> bA128
    // (exact reorder: (A^2 h) W2^T == A^2 (h W2^T), propagate at d=128)
    {
        dim3 grid(128 / 128, (N_NODES + 127) / 128);
        gemm_nt<256, 128, false><<<grid, 256>>>(2, W2, nullptr, 0);
    }

    // layer 2 propagation at d=128: bA128 -> bB128 -> d_out
    zero_kernel<<<ZB, 256>>>(nullptr, 1, n128_4);
    spmm128_kernel<<<SPMM_BLOCKS, 256>>>(nullptr, nullptr, 0, 1, er, ec, ev);
    zero_kernel<<<ZB, 256>>>((float4*)out, -1, n128_4);
    spmm128_kernel<<<SPMM_BLOCKS, 256>>>(nullptr, out, 1, -1, er, ec, ev);
}

// round 5
// speedup vs baseline: 3.5244x; 1.9049x over previous
#include <cuda_runtime.h>
#include <cstddef>

#define N_NODES 100000
#define NNZ     3200000
#define SCAN_B  1024
#define SCAN_NB ((N_NODES + SCAN_B - 1) / SCAN_B)   // 98

// ---------------- static scratch (no allocation allowed) ----------------
//   sel 0: bA128 = arena                  (N*128 floats)
//   sel 1: bB128 = arena + N*128          (N*128 floats)
//   sel 2: b256  = arena + N*256          (N*256 floats)
__device__ float g_scratch[(size_t)N_NODES * 512];
__device__ int2  g_packed[NNZ];            // row-sorted (col, val-bits)
__device__ int   g_rowptr[N_NODES + 1];
__device__ int   g_wptr[N_NODES];
__device__ int   g_counts[N_NODES];
__device__ int   g_bsum[SCAN_NB];

__device__ __forceinline__ float* buf(int sel) {
    switch (sel) {
        case 0:  return g_scratch;
        case 1:  return g_scratch + (size_t)N_NODES * 128;
        default: return g_scratch + (size_t)N_NODES * 256;
    }
}

// ================= CSR build =================
__global__ void zero_counts_kernel() {
    int i = blockIdx.x * blockDim.x + threadIdx.x;
    if (i < N_NODES) g_counts[i] = 0;
}

__global__ void hist_kernel(const int* __restrict__ rows) {
    int e = blockIdx.x * blockDim.x + threadIdx.x;
    if (e < NNZ) atomicAdd(&g_counts[rows[e]], 1);
}

// per-block inclusive scan (Hillis-Steele), emit exclusive prefix + block sum
__global__ void __launch_bounds__(SCAN_B) scan1_kernel() {
    __shared__ int sh[SCAN_B];
    int t = threadIdx.x;
    int i = blockIdx.x * SCAN_B + t;
    int v = (i < N_NODES) ? g_counts[i] : 0;
    sh[t] = v;
    __syncthreads();
    #pragma unroll
    for (int off = 1; off < SCAN_B; off <<= 1) {
        int add = (t >= off) ? sh[t - off] : 0;
        __syncthreads();
        sh[t] += add;
        __syncthreads();
    }
    if (i < N_NODES) g_rowptr[i] = sh[t] - v;   // exclusive, block-local
    if (t == SCAN_B - 1) g_bsum[blockIdx.x] = sh[t];
}

__global__ void scan2_kernel() {   // serial exclusive scan of 98 block sums
    if (threadIdx.x == 0) {
        int acc = 0;
        for (int b = 0; b < SCAN_NB; b++) {
            int s = g_bsum[b];
            g_bsum[b] = acc;
            acc += s;
        }
    }
}

__global__ void scan3_kernel() {
    int i = blockIdx.x * blockDim.x + threadIdx.x;
    if (i < N_NODES) {
        int off = g_rowptr[i] + g_bsum[i / SCAN_B];
        g_rowptr[i] = off;
        g_wptr[i]   = off;
    }
    if (i == 0) g_rowptr[N_NODES] = NNZ;
}

__global__ void scatter_kernel(const int* __restrict__ rows,
                               const int* __restrict__ cols,
                               const float* __restrict__ vals) {
    int e = blockIdx.x * blockDim.x + threadIdx.x;
    if (e < NNZ) {
        int r = rows[e];
        int pos = atomicAdd(&g_wptr[r], 1);
        g_packed[pos] = make_int2(cols[e], __float_as_int(vals[e]));
    }
}

// ================= SpMM (d=128), CSR gather, warp per row =================
__global__ void __launch_bounds__(256) spmm_csr_kernel(
    const float* __restrict__ h_ext,
    float*       __restrict__ out_ext,
    int in_sel, int out_sel)
{
    const float* h   = (in_sel  < 0) ? h_ext   : buf(in_sel);
    float*       out = (out_sel < 0) ? out_ext : buf(out_sel);

    int row  = (int)((blockIdx.x * blockDim.x + threadIdx.x) >> 5);
    int lane = threadIdx.x & 31;
    if (row >= N_NODES) return;

    int e   = g_rowptr[row];
    int end = g_rowptr[row + 1];

    float4 acc = make_float4(0.f, 0.f, 0.f, 0.f);

    // 4-edge unrolled main loop for memory-level parallelism
    for (; e + 4 <= end; e += 4) {
        int2 p0 = __ldg(&g_packed[e + 0]);
        int2 p1 = __ldg(&g_packed[e + 1]);
        int2 p2 = __ldg(&g_packed[e + 2]);
        int2 p3 = __ldg(&g_packed[e + 3]);
        float4 g0 = __ldg((const float4*)(h + (size_t)p0.x * 128) + lane);
        float4 g1 = __ldg((const float4*)(h + (size_t)p1.x * 128) + lane);
        float4 g2 = __ldg((const float4*)(h + (size_t)p2.x * 128) + lane);
        float4 g3 = __ldg((const float4*)(h + (size_t)p3.x * 128) + lane);
        float v0 = __int_as_float(p0.y), v1 = __int_as_float(p1.y);
        float v2 = __int_as_float(p2.y), v3 = __int_as_float(p3.y);
        acc.x += v0 * g0.x; acc.y += v0 * g0.y; acc.z += v0 * g0.z; acc.w += v0 * g0.w;
        acc.x += v1 * g1.x; acc.y += v1 * g1.y; acc.z += v1 * g1.z; acc.w += v1 * g1.w;
        acc.x += v2 * g2.x; acc.y += v2 * g2.y; acc.z += v2 * g2.z; acc.w += v2 * g2.w;
        acc.x += v3 * g3.x; acc.y += v3 * g3.y; acc.z += v3 * g3.z; acc.w += v3 * g3.w;
    }
    for (; e < end; e++) {
        int2 p = __ldg(&g_packed[e]);
        float v = __int_as_float(p.y);
        float4 g = __ldg((const float4*)(h + (size_t)p.x * 128) + lane);
        acc.x += v * g.x; acc.y += v * g.y; acc.z += v * g.z; acc.w += v * g.w;
    }

    ((float4*)(out + (size_t)row * 128))[lane] = acc;
}

// ---------------- GEMM: C[M,N] = act(A[M,K] @ W[N,K]^T) ----------------
// 128x128 block tile, BK=8, 8x8 micro-tile (4+4 split), 256 threads.
template<int K, int N, bool RELU>
__global__ void __launch_bounds__(256) gemm_nt(
    int a_sel,
    const float* __restrict__ W,
    float*       __restrict__ C_ext,
    int c_sel)
{
    const float* A = buf(a_sel);
    float*       C = (c_sel < 0) ? C_ext : buf(c_sel);

    constexpr int BM = 128, BN = 128, BK = 8;
    constexpr int M = N_NODES;
    __shared__ __align__(16) float As[BK][BM];
    __shared__ __align__(16) float Bs[BK][BN];

    int tid  = threadIdx.x;
    int row0 = blockIdx.y * BM;
    int col0 = blockIdx.x * BN;

    int lm = tid >> 1;           // 0..127
    int lk = (tid & 1) * 4;      // 0 or 4
    int ty = tid >> 4;           // 0..15
    int tx = tid & 15;           // 0..15

    float acc[2][2][4][4] = {};

    for (int k0 = 0; k0 < K; k0 += BK) {
        float4 av = make_float4(0.f, 0.f, 0.f, 0.f);
        int ar = row0 + lm;
        if (ar < M)
            av = *(const float4*)&A[(size_t)ar * K + k0 + lk];
        As[lk + 0][lm] = av.x; As[lk + 1][lm] = av.y;
        As[lk + 2][lm] = av.z; As[lk + 3][lm] = av.w;

        float4 bv = *(const float4*)&W[(size_t)(col0 + lm) * K + k0 + lk];
        Bs[lk + 0][lm] = bv.x; Bs[lk + 1][lm] = bv.y;
        Bs[lk + 2][lm] = bv.z; Bs[lk + 3][lm] = bv.w;

        __syncthreads();

        #pragma unroll
        for (int kk = 0; kk < BK; kk++) {
            float4 a0 = *(const float4*)&As[kk][ty * 4];
            float4 a1 = *(const float4*)&As[kk][64 + ty * 4];
            float4 b0 = *(const float4*)&Bs[kk][tx * 4];
            float4 b1 = *(const float4*)&Bs[kk][64 + tx * 4];
            float ar4[2][4] = {{a0.x, a0.y, a0.z, a0.w}, {a1.x, a1.y, a1.z, a1.w}};
            float br4[2][4] = {{b0.x, b0.y, b0.z, b0.w}, {b1.x, b1.y, b1.z, b1.w}};
            #pragma unroll
            for (int ri = 0; ri < 2; ri++)
                #pragma unroll
                for (int ci = 0; ci < 2; ci++)
                    #pragma unroll
                    for (int i = 0; i < 4; i++)
                        #pragma unroll
                        for (int j = 0; j < 4; j++)
                            acc[ri][ci][i][j] += ar4[ri][i] * br4[ci][j];
        }
        __syncthreads();
    }

    #pragma unroll
    for (int ri = 0; ri < 2; ri++) {
        #pragma unroll
        for (int i = 0; i < 4; i++) {
            int r = row0 + ri * 64 + ty * 4 + i;
            if (r < M) {
                #pragma unroll
                for (int ci = 0; ci < 2; ci++) {
                    float4 o;
                    o.x = acc[ri][ci][i][0]; o.y = acc[ri][ci][i][1];
                    o.z = acc[ri][ci][i][2]; o.w = acc[ri][ci][i][3];
                    if (RELU) {
                        o.x = fmaxf(o.x, 0.f); o.y = fmaxf(o.y, 0.f);
                        o.z = fmaxf(o.z, 0.f); o.w = fmaxf(o.w, 0.f);
                    }
                    *(float4*)&C[(size_t)r * N + col0 + ci * 64 + tx * 4] = o;
                }
            }
        }
    }
}

// ---------------- launch ----------------
extern "C" void kernel_launch(void* const* d_in, const int* in_sizes, int n_in,
                              void* d_out, int out_size)
{
    const float* x  = (const float*)d_in[0];
    const int*   er = (const int*)  d_in[1];
    const int*   ec = (const int*)  d_in[2];
    const float* ev = (const float*)d_in[3];
    const float* W1 = (const float*)d_in[4];
    const float* W2 = (const float*)d_in[5];
    float* out = (float*)d_out;

    const int NB_N   = (N_NODES + 255) / 256;
    const int NB_E   = (NNZ + 255) / 256;
    const int NB_ROW = (N_NODES * 32 + 255) / 256;   // warp per row

    // ---- build CSR (row-sorted packed edges) ----
    zero_counts_kernel<<<NB_N, 256>>>();
    hist_kernel<<<NB_E, 256>>>(er);
    scan1_kernel<<<SCAN_NB, SCAN_B>>>();
    scan2_kernel<<<1, 32>>>();
    scan3_kernel<<<NB_N, 256>>>();
    scatter_kernel<<<NB_E, 256>>>(er, ec, ev);

    // ---- layer 1 propagation: s = A (A x)   (d=128, gather-only) ----
    spmm_csr_kernel<<<NB_ROW, 256>>>(x, nullptr, -1, 0);
    spmm_csr_kernel<<<NB_ROW, 256>>>(nullptr, nullptr, 0, 1);

    // h = relu(s @ W1^T) : [100000,128] x [256,128]^T -> b256
    {
        dim3 grid(256 / 128, (N_NODES + 127) / 128);
        gemm_nt<128, 256, true><<<grid, 256>>>(1, W1, nullptr, 2);
    }

    // g = h @ W2^T : [100000,256] x [128,256]^T -> bA128
    // (exact reorder: (A^2 h) W2^T == A^2 (h W2^T), propagate at d=128)
    {
        dim3 grid(128 / 128, (N_NODES + 127) / 128);
        gemm_nt<256, 128, false><<<grid, 256>>>(2, W2, nullptr, 0);
    }

    // ---- layer 2 propagation: out = A (A g)   (d=128) ----
    spmm_csr_kernel<<<NB_ROW, 256>>>(nullptr, nullptr, 0, 1);
    spmm_csr_kernel<<<NB_ROW, 256>>>(nullptr, out, 1, -1);
}